// round 1
// baseline (speedup 1.0000x reference)
#include <cuda_runtime.h>
#include <math.h>

#define NN 50000
#define IN_DIM 256
#define HID 32
#define NCLS 40
#define NEDGE 1600000
#define NMID 30

// ---------------- device scratch (no allocations allowed) ----------------
__device__ int   g_degc[NN], g_degr[NN];
__device__ int   g_offc[NN + 1], g_offr[NN + 1];
__device__ int   g_curc[NN], g_curr[NN];
__device__ int   g_adjc[NEDGE], g_adjr[NEDGE];
__device__ float g_dinv[NN], g_cntinv[NN];
__device__ float g_x0[NN * HID];
__device__ float g_A [NN * HID];   // current h
__device__ float g_G [NN * HID];   // (h @ W) * dinv
__device__ float g_B [NN * HID];   // LN(relu(gcn)) output
__device__ float g_HM[NN * HID];   // mean_agg(h)
__device__ float g_V [NN * HID];   // |h - hm|
__device__ float g_G40[NN * NCLS]; // final (h @ Wl) * dinv

__device__ __forceinline__ float warpsum(float v) {
    #pragma unroll
    for (int o = 16; o > 0; o >>= 1) v += __shfl_xor_sync(0xffffffffu, v, o);
    return v;
}

// ---------------- setup: degrees, scans, CSR ----------------
__global__ void zero_deg() {
    for (int i = blockIdx.x * blockDim.x + threadIdx.x; i < NN;
         i += gridDim.x * blockDim.x) {
        g_degc[i] = 0;
        g_degr[i] = 0;
    }
}

__global__ void hist_edges(const int* __restrict__ ei) {
    for (int e = blockIdx.x * blockDim.x + threadIdx.x; e < NEDGE;
         e += gridDim.x * blockDim.x) {
        atomicAdd(&g_degr[ei[e]], 1);          // row
        atomicAdd(&g_degc[ei[NEDGE + e]], 1);  // col
    }
}

// one block, 1024 threads: exclusive scan of both degree arrays
__global__ void scan_two() {
    __shared__ int wsum[33];
    const int tid = threadIdx.x, lane = tid & 31, wid = tid >> 5;
    for (int arr = 0; arr < 2; arr++) {
        const int* src = arr ? g_degr : g_degc;
        int*       dst = arr ? g_offr : g_offc;
        int run = 0;
        for (int base = 0; base < NN; base += 1024) {
            int i = base + tid;
            int v = (i < NN) ? src[i] : 0;
            int inc = v;
            #pragma unroll
            for (int o = 1; o < 32; o <<= 1) {
                int t = __shfl_up_sync(0xffffffffu, inc, o);
                if (lane >= o) inc += t;
            }
            if (lane == 31) wsum[wid] = inc;
            __syncthreads();
            if (wid == 0) {
                int s = wsum[lane];
                int si = s;
                #pragma unroll
                for (int o = 1; o < 32; o <<= 1) {
                    int t = __shfl_up_sync(0xffffffffu, si, o);
                    if (lane >= o) si += t;
                }
                wsum[lane] = si - s;       // exclusive warp prefix
                if (lane == 31) wsum[32] = si;  // chunk total
            }
            __syncthreads();
            if (i < NN) dst[i] = run + wsum[wid] + inc - v;
            run += wsum[32];
            __syncthreads();
        }
        if (tid == 0) dst[NN] = run;
        __syncthreads();
    }
}

__global__ void node_init() {
    for (int i = blockIdx.x * blockDim.x + threadIdx.x; i < NN;
         i += gridDim.x * blockDim.x) {
        g_curc[i] = g_offc[i];
        g_curr[i] = g_offr[i];
        g_dinv[i] = rsqrtf((float)(g_degc[i] + 1));           // +1 self loop
        g_cntinv[i] = 1.0f / fmaxf((float)g_degr[i], 1.0f);
    }
}

__global__ void scatter_edges(const int* __restrict__ ei) {
    for (int e = blockIdx.x * blockDim.x + threadIdx.x; e < NEDGE;
         e += gridDim.x * blockDim.x) {
        int r = ei[e];
        int c = ei[NEDGE + e];
        int p = atomicAdd(&g_curc[c], 1);
        g_adjc[p] = r;  // CSR by col (gcn target), stores source row
        int q = atomicAdd(&g_curr[r], 1);
        g_adjr[q] = c;  // CSR by row (mean_agg target), stores source col
    }
}

// ---------------- first layer: x@W0*dinv -> G ; LN(relu(x@W_res)) -> x0 ----------------
__global__ void kfirst(const float* __restrict__ x, const float* __restrict__ W0,
                       const float* __restrict__ Wres, const float* __restrict__ rg,
                       const float* __restrict__ rb) {
    __shared__ float Wsm[IN_DIM * HID];  // 32 KB
    const int tid = threadIdx.x;
    const int lane = tid & 31;
    const int i = (blockIdx.x * blockDim.x + tid) >> 5;  // node (grid exact)

    for (int k = tid; k < IN_DIM * HID; k += blockDim.x) Wsm[k] = W0[k];

    float xr[8];
    #pragma unroll
    for (int j = 0; j < 8; j++) xr[j] = x[i * IN_DIM + j * 32 + lane];
    __syncthreads();

    float acc0 = 0.f;
    #pragma unroll
    for (int j = 0; j < 8; j++) {
        #pragma unroll
        for (int t = 0; t < 32; t++) {
            float xv = __shfl_sync(0xffffffffu, xr[j], t);
            acc0 = fmaf(xv, Wsm[(j * 32 + t) * HID + lane], acc0);
        }
    }
    __syncthreads();
    for (int k = tid; k < IN_DIM * HID; k += blockDim.x) Wsm[k] = Wres[k];
    __syncthreads();

    float acc1 = 0.f;
    #pragma unroll
    for (int j = 0; j < 8; j++) {
        #pragma unroll
        for (int t = 0; t < 32; t++) {
            float xv = __shfl_sync(0xffffffffu, xr[j], t);
            acc1 = fmaf(xv, Wsm[(j * 32 + t) * HID + lane], acc1);
        }
    }

    g_G[i * HID + lane] = acc0 * g_dinv[i];

    float r = fmaxf(acc1, 0.f);
    float m = warpsum(r) * (1.f / HID);
    float d = r - m;
    float var = warpsum(d * d) * (1.f / HID);
    g_x0[i * HID + lane] = d * rsqrtf(var + 1e-5f) * rg[lane] + rb[lane];
}

// ---------------- mid GEMM: A@W*dinv -> G ----------------
__global__ void k1_mid(const float* __restrict__ W) {
    __shared__ float Wsm[HID * HID];
    const int tid = threadIdx.x;
    const int lane = tid & 31;
    const int i = (blockIdx.x * blockDim.x + tid) >> 5;
    for (int k = tid; k < HID * HID; k += blockDim.x) Wsm[k] = W[k];
    __syncthreads();
    float hv = g_A[i * HID + lane];
    float acc = 0.f;
    #pragma unroll
    for (int t = 0; t < HID; t++)
        acc = fmaf(__shfl_sync(0xffffffffu, hv, t), Wsm[t * HID + lane], acc);
    g_G[i * HID + lane] = acc * g_dinv[i];
}

// ---------------- GCN aggregate + bias + relu + LN -> B ----------------
__global__ void k2_gcn_ln(const float* __restrict__ b, const float* __restrict__ gam,
                          const float* __restrict__ bet) {
    const int lane = threadIdx.x & 31;
    const int i = (blockIdx.x * blockDim.x + threadIdx.x) >> 5;
    if (i >= NN) return;
    float acc = g_G[i * HID + lane];  // self loop
    const int s = g_offc[i], e = g_offc[i + 1];
    int p = s;
    float a0 = 0.f, a1 = 0.f, a2 = 0.f, a3 = 0.f;
    for (; p + 3 < e; p += 4) {
        int i0 = g_adjc[p], i1 = g_adjc[p + 1], i2 = g_adjc[p + 2], i3 = g_adjc[p + 3];
        a0 += g_G[i0 * HID + lane];
        a1 += g_G[i1 * HID + lane];
        a2 += g_G[i2 * HID + lane];
        a3 += g_G[i3 * HID + lane];
    }
    for (; p < e; p++) acc += g_G[g_adjc[p] * HID + lane];
    acc += (a0 + a1) + (a2 + a3);
    float val = fmaxf(g_dinv[i] * acc + b[lane], 0.f);
    float m = warpsum(val) * (1.f / HID);
    float d = val - m;
    float var = warpsum(d * d) * (1.f / HID);
    g_B[i * HID + lane] = d * rsqrtf(var + 1e-5f) * gam[lane] + bet[lane];
}

// ---------------- mean_agg(B) -> HM ; V = |B - HM| ----------------
__global__ void k3_mean() {
    const int lane = threadIdx.x & 31;
    const int i = (blockIdx.x * blockDim.x + threadIdx.x) >> 5;
    if (i >= NN) return;
    const int s = g_offr[i], e = g_offr[i + 1];
    int p = s;
    float a0 = 0.f, a1 = 0.f, a2 = 0.f, a3 = 0.f, acc = 0.f;
    for (; p + 3 < e; p += 4) {
        int i0 = g_adjr[p], i1 = g_adjr[p + 1], i2 = g_adjr[p + 2], i3 = g_adjr[p + 3];
        a0 += g_B[i0 * HID + lane];
        a1 += g_B[i1 * HID + lane];
        a2 += g_B[i2 * HID + lane];
        a3 += g_B[i3 * HID + lane];
    }
    for (; p < e; p++) acc += g_B[g_adjr[p] * HID + lane];
    acc += (a0 + a1) + (a2 + a3);
    float hm = acc * g_cntinv[i];
    g_HM[i * HID + lane] = hm;
    g_V[i * HID + lane] = fabsf(g_B[i * HID + lane] - hm);
}

// ---------------- mean_agg(V) -> hstd ; score ; gate with x0 -> A ----------------
__global__ void k4_score(const float* __restrict__ w_ws) {
    const int lane = threadIdx.x & 31;
    const int i = (blockIdx.x * blockDim.x + threadIdx.x) >> 5;
    if (i >= NN) return;
    const int s = g_offr[i], e = g_offr[i + 1];
    int p = s;
    float a0 = 0.f, a1 = 0.f, a2 = 0.f, a3 = 0.f, acc = 0.f;
    for (; p + 3 < e; p += 4) {
        int i0 = g_adjr[p], i1 = g_adjr[p + 1], i2 = g_adjr[p + 2], i3 = g_adjr[p + 3];
        a0 += g_V[i0 * HID + lane];
        a1 += g_V[i1 * HID + lane];
        a2 += g_V[i2 * HID + lane];
        a3 += g_V[i3 * HID + lane];
    }
    for (; p < e; p++) acc += g_V[g_adjr[p] * HID + lane];
    acc += (a0 + a1) + (a2 + a3);
    float hstd = acc * g_cntinv[i];
    float h = g_B[i * HID + lane];
    float hm = g_HM[i * HID + lane];
    float part = hm * h * w_ws[lane] + hstd * w_ws[32 + lane] + h * w_ws[64 + lane];
    float sc = warpsum(part);
    sc = 1.0f / (1.0f + expf(-sc));
    g_A[i * HID + lane] = (1.0f - sc) * h + sc * g_x0[i * HID + lane];
}

// ---------------- final classifier GEMM: A@Wl*dinv -> G40 ----------------
__global__ void k1_final(const float* __restrict__ Wl) {
    __shared__ float Wsm[HID * NCLS];
    const int tid = threadIdx.x;
    const int lane = tid & 31;
    const int i = (blockIdx.x * blockDim.x + tid) >> 5;
    for (int k = tid; k < HID * NCLS; k += blockDim.x) Wsm[k] = Wl[k];
    __syncthreads();
    float hv = g_A[i * HID + lane];
    float acc0 = 0.f, acc1 = 0.f;
    #pragma unroll
    for (int t = 0; t < HID; t++) {
        float xv = __shfl_sync(0xffffffffu, hv, t);
        acc0 = fmaf(xv, Wsm[t * NCLS + lane], acc0);
        if (lane < 8) acc1 = fmaf(xv, Wsm[t * NCLS + 32 + lane], acc1);
    }
    float dv = g_dinv[i];
    g_G40[i * NCLS + lane] = acc0 * dv;
    if (lane < 8) g_G40[i * NCLS + 32 + lane] = acc1 * dv;
}

// ---------------- final GCN aggregate -> out ----------------
__global__ void k2_final(const float* __restrict__ bl, float* __restrict__ out) {
    const int lane = threadIdx.x & 31;
    const int i = (blockIdx.x * blockDim.x + threadIdx.x) >> 5;
    if (i >= NN) return;
    float acc0 = g_G40[i * NCLS + lane];
    float acc1 = (lane < 8) ? g_G40[i * NCLS + 32 + lane] : 0.f;
    const int s = g_offc[i], e = g_offc[i + 1];
    for (int p = s; p < e; p++) {
        int idx = g_adjc[p];
        acc0 += g_G40[idx * NCLS + lane];
        if (lane < 8) acc1 += g_G40[idx * NCLS + 32 + lane];
    }
    float dv = g_dinv[i];
    out[i * NCLS + lane] = dv * acc0 + bl[lane];
    if (lane < 8) out[i * NCLS + 32 + lane] = dv * acc1 + bl[32 + lane];
}

// ---------------- host ----------------
extern "C" void kernel_launch(void* const* d_in, const int* in_sizes, int n_in,
                              void* d_out, int out_size) {
    const float* x    = (const float*)d_in[0];
    const int*   ei   = (const int*)d_in[1];
    const float* W0   = (const float*)d_in[2];
    const float* b0   = (const float*)d_in[3];
    const float* Whh  = (const float*)d_in[4];
    const float* bhh  = (const float*)d_in[5];
    const float* Wl   = (const float*)d_in[6];
    const float* bl   = (const float*)d_in[7];
    const float* lng0 = (const float*)d_in[8];
    const float* lnb0 = (const float*)d_in[9];
    const float* lngm = (const float*)d_in[10];
    const float* lnbm = (const float*)d_in[11];
    const float* w_ws = (const float*)d_in[12];
    const float* Wres = (const float*)d_in[13];
    const float* rg   = (const float*)d_in[14];
    const float* rb   = (const float*)d_in[15];
    float* out = (float*)d_out;

    const int nodeBlocks = (NN + 255) / 256;
    const int warpBlocks = (NN * 32 + 255) / 256;  // warp-per-node, 8 nodes/block

    // CSR build
    zero_deg<<<nodeBlocks, 256>>>();
    hist_edges<<<2048, 256>>>(ei);
    scan_two<<<1, 1024>>>();
    node_init<<<nodeBlocks, 256>>>();
    scatter_edges<<<2048, 256>>>(ei);

    // first layer
    kfirst<<<warpBlocks, 256>>>(x, W0, Wres, rg, rb);

    for (int l = 0; l <= NMID; l++) {  // blocks 0..30
        const float* b   = (l == 0) ? b0   : bhh  + (l - 1) * HID;
        const float* gam = (l == 0) ? lng0 : lngm + (l - 1) * HID;
        const float* bet = (l == 0) ? lnb0 : lnbm + (l - 1) * HID;
        k2_gcn_ln<<<warpBlocks, 256>>>(b, gam, bet);
        k3_mean<<<warpBlocks, 256>>>();
        k4_score<<<warpBlocks, 256>>>(w_ws);
        if (l < NMID) {
            k1_mid<<<warpBlocks, 256>>>(Whh + l * HID * HID);
        }
    }
    k1_final<<<warpBlocks, 256>>>(Wl);
    k2_final<<<warpBlocks, 256>>>(bl, out);
}

// round 3
// speedup vs baseline: 1.0214x; 1.0214x over previous
#include <cuda_runtime.h>
#include <cuda_fp16.h>
#include <math.h>

#define NN 50000
#define IN_DIM 256
#define HID 32
#define NCLS 40
#define NEDGE 1600000
#define NMID 30

// ---------------- device scratch (no allocations allowed) ----------------
__device__ int    g_degc[NN], g_degr[NN];
__device__ int    g_offc[NN + 1], g_offr[NN + 1];
__device__ int    g_curc[NN], g_curr[NN];
__device__ int    g_adjc[NEDGE], g_adjr[NEDGE];
__device__ float  g_dinv[NN], g_cntinv[NN];
__device__ float  g_x0[NN * HID];
__device__ float  g_A [NN * HID];    // final-layer input (written once)
__device__ float  g_G [NN * HID];    // (h @ W) * dinv   — gathered (fp32: precision-critical)
__device__ float  g_Bf[NN * HID];    // LN(relu(gcn))    — node-local fp32
__device__ __half g_Bh[NN * HID];    // fp16 gather copy (score path only)
__device__ float  g_HM[NN * HID];    // mean_agg(h)      — node-local
__device__ __half g_V [NN * HID];    // |h - hm|         — gathered fp16 (score path only)
__device__ float  g_G40[NN * NCLS];  // final (h @ Wl) * dinv

__device__ __forceinline__ float warpsum(float v) {
    #pragma unroll
    for (int o = 16; o > 0; o >>= 1) v += __shfl_xor_sync(0xffffffffu, v, o);
    return v;
}

// ---------------- setup: degrees, scans, CSR ----------------
__global__ void zero_deg() {
    for (int i = blockIdx.x * blockDim.x + threadIdx.x; i < NN;
         i += gridDim.x * blockDim.x) {
        g_degc[i] = 0;
        g_degr[i] = 0;
    }
}

__global__ void hist_edges(const int* __restrict__ ei) {
    for (int e = blockIdx.x * blockDim.x + threadIdx.x; e < NEDGE;
         e += gridDim.x * blockDim.x) {
        atomicAdd(&g_degr[ei[e]], 1);          // row
        atomicAdd(&g_degc[ei[NEDGE + e]], 1);  // col
    }
}

// one block, 1024 threads: exclusive scan of both degree arrays
__global__ void scan_two() {
    __shared__ int wsum[33];
    const int tid = threadIdx.x, lane = tid & 31, wid = tid >> 5;
    for (int arr = 0; arr < 2; arr++) {
        const int* src = arr ? g_degr : g_degc;
        int*       dst = arr ? g_offr : g_offc;
        int run = 0;
        for (int base = 0; base < NN; base += 1024) {
            int i = base + tid;
            int v = (i < NN) ? src[i] : 0;
            int inc = v;
            #pragma unroll
            for (int o = 1; o < 32; o <<= 1) {
                int t = __shfl_up_sync(0xffffffffu, inc, o);
                if (lane >= o) inc += t;
            }
            if (lane == 31) wsum[wid] = inc;
            __syncthreads();
            if (wid == 0) {
                int s = wsum[lane];
                int si = s;
                #pragma unroll
                for (int o = 1; o < 32; o <<= 1) {
                    int t = __shfl_up_sync(0xffffffffu, si, o);
                    if (lane >= o) si += t;
                }
                wsum[lane] = si - s;            // exclusive warp prefix
                if (lane == 31) wsum[32] = si;  // chunk total
            }
            __syncthreads();
            if (i < NN) dst[i] = run + wsum[wid] + inc - v;
            run += wsum[32];
            __syncthreads();
        }
        if (tid == 0) dst[NN] = run;
        __syncthreads();
    }
}

__global__ void node_init() {
    for (int i = blockIdx.x * blockDim.x + threadIdx.x; i < NN;
         i += gridDim.x * blockDim.x) {
        g_curc[i] = g_offc[i];
        g_curr[i] = g_offr[i];
        g_dinv[i] = rsqrtf((float)(g_degc[i] + 1));  // +1 self loop
        g_cntinv[i] = 1.0f / fmaxf((float)g_degr[i], 1.0f);
    }
}

__global__ void scatter_edges(const int* __restrict__ ei) {
    for (int e = blockIdx.x * blockDim.x + threadIdx.x; e < NEDGE;
         e += gridDim.x * blockDim.x) {
        int r = ei[e];
        int c = ei[NEDGE + e];
        int p = atomicAdd(&g_curc[c], 1);
        g_adjc[p] = r;  // CSR by col (gcn target), stores source row
        int q = atomicAdd(&g_curr[r], 1);
        g_adjr[q] = c;  // CSR by row (mean_agg target), stores source col
    }
}

// ---------------- first layer: x@W0*dinv -> G ; LN(relu(x@W_res)) -> x0 ----------------
__global__ void kfirst(const float* __restrict__ x, const float* __restrict__ W0,
                       const float* __restrict__ Wres, const float* __restrict__ rg,
                       const float* __restrict__ rb) {
    __shared__ float Wsm[IN_DIM * HID];  // 32 KB
    const int tid = threadIdx.x;
    const int lane = tid & 31;
    const int i = (blockIdx.x * blockDim.x + tid) >> 5;  // node (grid exact)

    for (int k = tid; k < IN_DIM * HID; k += blockDim.x) Wsm[k] = W0[k];

    float xr[8];
    #pragma unroll
    for (int j = 0; j < 8; j++) xr[j] = x[i * IN_DIM + j * 32 + lane];
    __syncthreads();

    float acc0 = 0.f;
    #pragma unroll
    for (int j = 0; j < 8; j++) {
        #pragma unroll
        for (int t = 0; t < 32; t++) {
            float xv = __shfl_sync(0xffffffffu, xr[j], t);
            acc0 = fmaf(xv, Wsm[(j * 32 + t) * HID + lane], acc0);
        }
    }
    __syncthreads();
    for (int k = tid; k < IN_DIM * HID; k += blockDim.x) Wsm[k] = Wres[k];
    __syncthreads();

    float acc1 = 0.f;
    #pragma unroll
    for (int j = 0; j < 8; j++) {
        #pragma unroll
        for (int t = 0; t < 32; t++) {
            float xv = __shfl_sync(0xffffffffu, xr[j], t);
            acc1 = fmaf(xv, Wsm[(j * 32 + t) * HID + lane], acc1);
        }
    }

    g_G[i * HID + lane] = acc0 * g_dinv[i];

    float r = fmaxf(acc1, 0.f);
    float m = warpsum(r) * (1.f / HID);
    float d = r - m;
    float var = warpsum(d * d) * (1.f / HID);
    g_x0[i * HID + lane] = d * rsqrtf(var + 1e-5f) * rg[lane] + rb[lane];
}

// ---------------- GCN aggregate + bias + relu + LN -> Bf/Bh ----------------
__global__ void k2_gcn_ln(const float* __restrict__ b, const float* __restrict__ gam,
                          const float* __restrict__ bet) {
    const int lane = threadIdx.x & 31;
    const int i = (blockIdx.x * blockDim.x + threadIdx.x) >> 5;
    if (i >= NN) return;
    float acc = g_G[i * HID + lane];  // self loop
    const int s = g_offc[i], e = g_offc[i + 1];
    int p = s;
    float a0 = 0.f, a1 = 0.f, a2 = 0.f, a3 = 0.f;
    for (; p + 3 < e; p += 4) {
        int i0 = g_adjc[p], i1 = g_adjc[p + 1], i2 = g_adjc[p + 2], i3 = g_adjc[p + 3];
        a0 += g_G[i0 * HID + lane];
        a1 += g_G[i1 * HID + lane];
        a2 += g_G[i2 * HID + lane];
        a3 += g_G[i3 * HID + lane];
    }
    for (; p < e; p++) acc += g_G[g_adjc[p] * HID + lane];
    acc += (a0 + a1) + (a2 + a3);
    float val = fmaxf(g_dinv[i] * acc + b[lane], 0.f);
    float m = warpsum(val) * (1.f / HID);
    float d = val - m;
    float var = warpsum(d * d) * (1.f / HID);
    float o = d * rsqrtf(var + 1e-5f) * gam[lane] + bet[lane];
    g_Bf[i * HID + lane] = o;
    g_Bh[i * HID + lane] = __float2half_rn(o);
}

// ---------------- mean_agg(B) -> HM ; V = |B - HM| ----------------
__global__ void k3_mean() {
    const int lane = threadIdx.x & 31;
    const int i = (blockIdx.x * blockDim.x + threadIdx.x) >> 5;
    if (i >= NN) return;
    const int s = g_offr[i], e = g_offr[i + 1];
    int p = s;
    float a0 = 0.f, a1 = 0.f, a2 = 0.f, a3 = 0.f, acc = 0.f;
    for (; p + 3 < e; p += 4) {
        int i0 = g_adjr[p], i1 = g_adjr[p + 1], i2 = g_adjr[p + 2], i3 = g_adjr[p + 3];
        a0 += __half2float(g_Bh[i0 * HID + lane]);
        a1 += __half2float(g_Bh[i1 * HID + lane]);
        a2 += __half2float(g_Bh[i2 * HID + lane]);
        a3 += __half2float(g_Bh[i3 * HID + lane]);
    }
    for (; p < e; p++) acc += __half2float(g_Bh[g_adjr[p] * HID + lane]);
    acc += (a0 + a1) + (a2 + a3);
    float hm = acc * g_cntinv[i];
    g_HM[i * HID + lane] = hm;
    g_V[i * HID + lane] = __float2half_rn(fabsf(g_Bf[i * HID + lane] - hm));
}

// ---------------- mean_agg(V) -> hstd ; score ; gate ; fused GEMM -> G ----------------
__global__ void k4_score_gemm(const float* __restrict__ w_ws, const float* __restrict__ W) {
    __shared__ float Wsm[HID * HID];
    const int tid = threadIdx.x;
    const int lane = tid & 31;
    const int i = (blockIdx.x * blockDim.x + tid) >> 5;
    for (int k = tid; k < HID * HID; k += blockDim.x) Wsm[k] = W[k];
    __syncthreads();
    if (i >= NN) return;
    const int s = g_offr[i], e = g_offr[i + 1];
    int p = s;
    float a0 = 0.f, a1 = 0.f, a2 = 0.f, a3 = 0.f, acc = 0.f;
    for (; p + 3 < e; p += 4) {
        int i0 = g_adjr[p], i1 = g_adjr[p + 1], i2 = g_adjr[p + 2], i3 = g_adjr[p + 3];
        a0 += __half2float(g_V[i0 * HID + lane]);
        a1 += __half2float(g_V[i1 * HID + lane]);
        a2 += __half2float(g_V[i2 * HID + lane]);
        a3 += __half2float(g_V[i3 * HID + lane]);
    }
    for (; p < e; p++) acc += __half2float(g_V[g_adjr[p] * HID + lane]);
    acc += (a0 + a1) + (a2 + a3);
    float hstd = acc * g_cntinv[i];
    float h = g_Bf[i * HID + lane];
    float hm = g_HM[i * HID + lane];
    float part = hm * h * w_ws[lane] + hstd * w_ws[32 + lane] + h * w_ws[64 + lane];
    float sc = warpsum(part);
    sc = 1.0f / (1.0f + expf(-sc));
    float hnew = (1.0f - sc) * h + sc * g_x0[i * HID + lane];
    // fused next-layer GEMM: G = (hnew @ W) * dinv
    float g = 0.f;
    #pragma unroll
    for (int t = 0; t < HID; t++)
        g = fmaf(__shfl_sync(0xffffffffu, hnew, t), Wsm[t * HID + lane], g);
    g_G[i * HID + lane] = g * g_dinv[i];
}

// ---------------- last block: same but writes A (fp32) for the classifier ----------------
__global__ void k4_score_last(const float* __restrict__ w_ws) {
    const int lane = threadIdx.x & 31;
    const int i = (blockIdx.x * blockDim.x + threadIdx.x) >> 5;
    if (i >= NN) return;
    const int s = g_offr[i], e = g_offr[i + 1];
    int p = s;
    float a0 = 0.f, a1 = 0.f, a2 = 0.f, a3 = 0.f, acc = 0.f;
    for (; p + 3 < e; p += 4) {
        int i0 = g_adjr[p], i1 = g_adjr[p + 1], i2 = g_adjr[p + 2], i3 = g_adjr[p + 3];
        a0 += __half2float(g_V[i0 * HID + lane]);
        a1 += __half2float(g_V[i1 * HID + lane]);
        a2 += __half2float(g_V[i2 * HID + lane]);
        a3 += __half2float(g_V[i3 * HID + lane]);
    }
    for (; p < e; p++) acc += __half2float(g_V[g_adjr[p] * HID + lane]);
    acc += (a0 + a1) + (a2 + a3);
    float hstd = acc * g_cntinv[i];
    float h = g_Bf[i * HID + lane];
    float hm = g_HM[i * HID + lane];
    float part = hm * h * w_ws[lane] + hstd * w_ws[32 + lane] + h * w_ws[64 + lane];
    float sc = warpsum(part);
    sc = 1.0f / (1.0f + expf(-sc));
    g_A[i * HID + lane] = (1.0f - sc) * h + sc * g_x0[i * HID + lane];
}

// ---------------- final classifier GEMM: A@Wl*dinv -> G40 ----------------
__global__ void k1_final(const float* __restrict__ Wl) {
    __shared__ float Wsm[HID * NCLS];
    const int tid = threadIdx.x;
    const int lane = tid & 31;
    const int i = (blockIdx.x * blockDim.x + tid) >> 5;
    for (int k = tid; k < HID * NCLS; k += blockDim.x) Wsm[k] = Wl[k];
    __syncthreads();
    float hv = g_A[i * HID + lane];
    float acc0 = 0.f, acc1 = 0.f;
    #pragma unroll
    for (int t = 0; t < HID; t++) {
        float xv = __shfl_sync(0xffffffffu, hv, t);
        acc0 = fmaf(xv, Wsm[t * NCLS + lane], acc0);
        if (lane < 8) acc1 = fmaf(xv, Wsm[t * NCLS + 32 + lane], acc1);
    }
    float dv = g_dinv[i];
    g_G40[i * NCLS + lane] = acc0 * dv;
    if (lane < 8) g_G40[i * NCLS + 32 + lane] = acc1 * dv;
}

// ---------------- final GCN aggregate -> out ----------------
__global__ void k2_final(const float* __restrict__ bl, float* __restrict__ out) {
    const int lane = threadIdx.x & 31;
    const int i = (blockIdx.x * blockDim.x + threadIdx.x) >> 5;
    if (i >= NN) return;
    float acc0 = g_G40[i * NCLS + lane];
    float acc1 = (lane < 8) ? g_G40[i * NCLS + 32 + lane] : 0.f;
    const int s = g_offc[i], e = g_offc[i + 1];
    for (int p = s; p < e; p++) {
        int idx = g_adjc[p];
        acc0 += g_G40[idx * NCLS + lane];
        if (lane < 8) acc1 += g_G40[idx * NCLS + 32 + lane];
    }
    float dv = g_dinv[i];
    out[i * NCLS + lane] = dv * acc0 + bl[lane];
    if (lane < 8) out[i * NCLS + 32 + lane] = dv * acc1 + bl[32 + lane];
}

// ---------------- host ----------------
extern "C" void kernel_launch(void* const* d_in, const int* in_sizes, int n_in,
                              void* d_out, int out_size) {
    const float* x    = (const float*)d_in[0];
    const int*   ei   = (const int*)d_in[1];
    const float* W0   = (const float*)d_in[2];
    const float* b0   = (const float*)d_in[3];
    const float* Whh  = (const float*)d_in[4];
    const float* bhh  = (const float*)d_in[5];
    const float* Wl   = (const float*)d_in[6];
    const float* bl   = (const float*)d_in[7];
    const float* lng0 = (const float*)d_in[8];
    const float* lnb0 = (const float*)d_in[9];
    const float* lngm = (const float*)d_in[10];
    const float* lnbm = (const float*)d_in[11];
    const float* w_ws = (const float*)d_in[12];
    const float* Wres = (const float*)d_in[13];
    const float* rg   = (const float*)d_in[14];
    const float* rb   = (const float*)d_in[15];
    float* out = (float*)d_out;

    const int nodeBlocks = (NN + 255) / 256;
    const int warpBlocks = (NN * 32 + 255) / 256;  // warp-per-node, 8 nodes/block

    // CSR build
    zero_deg<<<nodeBlocks, 256>>>();
    hist_edges<<<2048, 256>>>(ei);
    scan_two<<<1, 1024>>>();
    node_init<<<nodeBlocks, 256>>>();
    scatter_edges<<<2048, 256>>>(ei);

    // first layer
    kfirst<<<warpBlocks, 256>>>(x, W0, Wres, rg, rb);

    for (int l = 0; l <= NMID; l++) {  // blocks 0..30
        const float* b   = (l == 0) ? b0   : bhh  + (l - 1) * HID;
        const float* gam = (l == 0) ? lng0 : lngm + (l - 1) * HID;
        const float* bet = (l == 0) ? lnb0 : lnbm + (l - 1) * HID;
        k2_gcn_ln<<<warpBlocks, 256>>>(b, gam, bet);
        k3_mean<<<warpBlocks, 256>>>();
        if (l < NMID) {
            k4_score_gemm<<<warpBlocks, 256>>>(w_ws, Whh + l * HID * HID);
        } else {
            k4_score_last<<<warpBlocks, 256>>>(w_ws);
        }
    }
    k1_final<<<warpBlocks, 256>>>(Wl);
    k2_final<<<warpBlocks, 256>>>(bl, out);
}

// round 4
// speedup vs baseline: 1.1836x; 1.1587x over previous
#include <cuda_runtime.h>
#include <cuda_fp16.h>
#include <math.h>

#define NN 50000
#define IN_DIM 256
#define HID 32
#define NCLS 40
#define NEDGE 1600000
#define NMID 30

// ---------------- device scratch (no allocations allowed) ----------------
__device__ int    g_degc[NN], g_degr[NN];
__device__ int    g_offc[NN + 1], g_offr[NN + 1];
__device__ int    g_curc[NN], g_curr[NN];
__device__ int    g_adjc[NEDGE], g_adjr[NEDGE];
__device__ float  g_dinv[NN], g_cntinv[NN];
__device__ float  g_x0[NN * HID];
__device__ float  g_A [NN * HID];    // final-layer input (written once)
__device__ float  g_G [NN * HID];    // (h @ W) * dinv   — gathered fp32 (precision-critical)
__device__ float  g_Bf[NN * HID];    // LN(relu(gcn))    — node-local fp32
__device__ __half g_Bh[NN * HID];    // fp16 gather copy (score path only)
__device__ float  g_S[NN];           // s[j]=Σ|B-hm|·w2  — scalar gathered fp32
__device__ float  g_T[NN];           // t[i]=Σ hm·h·w0   — node-local scalar
__device__ float  g_G40[NN * NCLS];  // final (h @ Wl) * dinv

__device__ __forceinline__ float warpsum(float v) {
    #pragma unroll
    for (int o = 16; o > 0; o >>= 1) v += __shfl_xor_sync(0xffffffffu, v, o);
    return v;
}

// ---------------- setup: degrees, scans, CSR ----------------
__global__ void zero_deg() {
    for (int i = blockIdx.x * blockDim.x + threadIdx.x; i < NN;
         i += gridDim.x * blockDim.x) {
        g_degc[i] = 0;
        g_degr[i] = 0;
    }
}

__global__ void hist_edges(const int* __restrict__ ei) {
    for (int e = blockIdx.x * blockDim.x + threadIdx.x; e < NEDGE;
         e += gridDim.x * blockDim.x) {
        atomicAdd(&g_degr[ei[e]], 1);          // row
        atomicAdd(&g_degc[ei[NEDGE + e]], 1);  // col
    }
}

// one block, 1024 threads: exclusive scan of both degree arrays
__global__ void scan_two() {
    __shared__ int wsum[33];
    const int tid = threadIdx.x, lane = tid & 31, wid = tid >> 5;
    for (int arr = 0; arr < 2; arr++) {
        const int* src = arr ? g_degr : g_degc;
        int*       dst = arr ? g_offr : g_offc;
        int run = 0;
        for (int base = 0; base < NN; base += 1024) {
            int i = base + tid;
            int v = (i < NN) ? src[i] : 0;
            int inc = v;
            #pragma unroll
            for (int o = 1; o < 32; o <<= 1) {
                int t = __shfl_up_sync(0xffffffffu, inc, o);
                if (lane >= o) inc += t;
            }
            if (lane == 31) wsum[wid] = inc;
            __syncthreads();
            if (wid == 0) {
                int s = wsum[lane];
                int si = s;
                #pragma unroll
                for (int o = 1; o < 32; o <<= 1) {
                    int t = __shfl_up_sync(0xffffffffu, si, o);
                    if (lane >= o) si += t;
                }
                wsum[lane] = si - s;            // exclusive warp prefix
                if (lane == 31) wsum[32] = si;  // chunk total
            }
            __syncthreads();
            if (i < NN) dst[i] = run + wsum[wid] + inc - v;
            run += wsum[32];
            __syncthreads();
        }
        if (tid == 0) dst[NN] = run;
        __syncthreads();
    }
}

__global__ void node_init() {
    for (int i = blockIdx.x * blockDim.x + threadIdx.x; i < NN;
         i += gridDim.x * blockDim.x) {
        g_curc[i] = g_offc[i];
        g_curr[i] = g_offr[i];
        g_dinv[i] = rsqrtf((float)(g_degc[i] + 1));  // +1 self loop
        g_cntinv[i] = 1.0f / fmaxf((float)g_degr[i], 1.0f);
    }
}

__global__ void scatter_edges(const int* __restrict__ ei) {
    for (int e = blockIdx.x * blockDim.x + threadIdx.x; e < NEDGE;
         e += gridDim.x * blockDim.x) {
        int r = ei[e];
        int c = ei[NEDGE + e];
        int p = atomicAdd(&g_curc[c], 1);
        g_adjc[p] = r;  // CSR by col (gcn target), stores source row
        int q = atomicAdd(&g_curr[r], 1);
        g_adjr[q] = c;  // CSR by row (mean_agg target), stores source col
    }
}

// ---------------- first layer: x@W0*dinv -> G ; LN(relu(x@W_res)) -> x0 ----------------
__global__ void kfirst(const float* __restrict__ x, const float* __restrict__ W0,
                       const float* __restrict__ Wres, const float* __restrict__ rg,
                       const float* __restrict__ rb) {
    __shared__ float Wsm[IN_DIM * HID];  // 32 KB
    const int tid = threadIdx.x;
    const int lane = tid & 31;
    const int i = (blockIdx.x * blockDim.x + tid) >> 5;  // node (grid exact)

    for (int k = tid; k < IN_DIM * HID; k += blockDim.x) Wsm[k] = W0[k];

    float xr[8];
    #pragma unroll
    for (int j = 0; j < 8; j++) xr[j] = x[i * IN_DIM + j * 32 + lane];
    __syncthreads();

    float acc0 = 0.f;
    #pragma unroll
    for (int j = 0; j < 8; j++) {
        #pragma unroll
        for (int t = 0; t < 32; t++) {
            float xv = __shfl_sync(0xffffffffu, xr[j], t);
            acc0 = fmaf(xv, Wsm[(j * 32 + t) * HID + lane], acc0);
        }
    }
    __syncthreads();
    for (int k = tid; k < IN_DIM * HID; k += blockDim.x) Wsm[k] = Wres[k];
    __syncthreads();

    float acc1 = 0.f;
    #pragma unroll
    for (int j = 0; j < 8; j++) {
        #pragma unroll
        for (int t = 0; t < 32; t++) {
            float xv = __shfl_sync(0xffffffffu, xr[j], t);
            acc1 = fmaf(xv, Wsm[(j * 32 + t) * HID + lane], acc1);
        }
    }

    g_G[i * HID + lane] = acc0 * g_dinv[i];

    float r = fmaxf(acc1, 0.f);
    float m = warpsum(r) * (1.f / HID);
    float d = r - m;
    float var = warpsum(d * d) * (1.f / HID);
    g_x0[i * HID + lane] = d * rsqrtf(var + 1e-5f) * rg[lane] + rb[lane];
}

// ---------------- GCN aggregate + bias + relu + LN -> Bf/Bh ----------------
__global__ void k2_gcn_ln(const float* __restrict__ b, const float* __restrict__ gam,
                          const float* __restrict__ bet) {
    const int lane = threadIdx.x & 31;
    const int i = (blockIdx.x * blockDim.x + threadIdx.x) >> 5;
    if (i >= NN) return;
    float acc = g_G[i * HID + lane];  // self loop
    const int s = g_offc[i], e = g_offc[i + 1];
    int p = s;
    float a0 = 0.f, a1 = 0.f, a2 = 0.f, a3 = 0.f;
    float a4 = 0.f, a5 = 0.f, a6 = 0.f, a7 = 0.f;
    for (; p + 8 <= e; p += 8) {
        int i0 = g_adjc[p],     i1 = g_adjc[p + 1], i2 = g_adjc[p + 2], i3 = g_adjc[p + 3];
        int i4 = g_adjc[p + 4], i5 = g_adjc[p + 5], i6 = g_adjc[p + 6], i7 = g_adjc[p + 7];
        a0 += g_G[i0 * HID + lane];
        a1 += g_G[i1 * HID + lane];
        a2 += g_G[i2 * HID + lane];
        a3 += g_G[i3 * HID + lane];
        a4 += g_G[i4 * HID + lane];
        a5 += g_G[i5 * HID + lane];
        a6 += g_G[i6 * HID + lane];
        a7 += g_G[i7 * HID + lane];
    }
    for (; p < e; p++) acc += g_G[g_adjc[p] * HID + lane];
    acc += ((a0 + a1) + (a2 + a3)) + ((a4 + a5) + (a6 + a7));
    float val = fmaxf(g_dinv[i] * acc + b[lane], 0.f);
    float m = warpsum(val) * (1.f / HID);
    float d = val - m;
    float var = warpsum(d * d) * (1.f / HID);
    float o = d * rsqrtf(var + 1e-5f) * gam[lane] + bet[lane];
    g_Bf[i * HID + lane] = o;
    g_Bh[i * HID + lane] = __float2half_rn(o);
}

// ---------------- mean_agg(B) -> hm ; scalars s=Σ|B-hm|·w2, t=Σ hm·h·w0 ----------------
__global__ void k3_mean(const float* __restrict__ w_ws) {
    const int lane = threadIdx.x & 31;
    const int i = (blockIdx.x * blockDim.x + threadIdx.x) >> 5;
    if (i >= NN) return;
    const int s = g_offr[i], e = g_offr[i + 1];
    int p = s;
    float a0 = 0.f, a1 = 0.f, a2 = 0.f, a3 = 0.f;
    float a4 = 0.f, a5 = 0.f, a6 = 0.f, a7 = 0.f, acc = 0.f;
    for (; p + 8 <= e; p += 8) {
        int i0 = g_adjr[p],     i1 = g_adjr[p + 1], i2 = g_adjr[p + 2], i3 = g_adjr[p + 3];
        int i4 = g_adjr[p + 4], i5 = g_adjr[p + 5], i6 = g_adjr[p + 6], i7 = g_adjr[p + 7];
        a0 += __half2float(g_Bh[i0 * HID + lane]);
        a1 += __half2float(g_Bh[i1 * HID + lane]);
        a2 += __half2float(g_Bh[i2 * HID + lane]);
        a3 += __half2float(g_Bh[i3 * HID + lane]);
        a4 += __half2float(g_Bh[i4 * HID + lane]);
        a5 += __half2float(g_Bh[i5 * HID + lane]);
        a6 += __half2float(g_Bh[i6 * HID + lane]);
        a7 += __half2float(g_Bh[i7 * HID + lane]);
    }
    for (; p < e; p++) acc += __half2float(g_Bh[g_adjr[p] * HID + lane]);
    acc += ((a0 + a1) + (a2 + a3)) + ((a4 + a5) + (a6 + a7));
    float hm = acc * g_cntinv[i];
    float h = g_Bf[i * HID + lane];
    float sv = warpsum(fabsf(h - hm) * w_ws[32 + lane]);  // hstd·w2 contribution of node i
    float tv = warpsum(hm * h * w_ws[lane]);              // hm⊙h·w0 term for node i
    if (lane == 0) {
        g_S[i] = sv;
        g_T[i] = tv;
    }
}

// ---------------- scalar gather s -> hd ; score ; gate ; fused GEMM -> G ----------------
__global__ void k4_score_gemm(const float* __restrict__ w_ws, const float* __restrict__ W) {
    __shared__ float Wsm[HID * HID];
    const int tid = threadIdx.x;
    const int lane = tid & 31;
    const int i = (blockIdx.x * blockDim.x + tid) >> 5;
    for (int k = tid; k < HID * HID; k += blockDim.x) Wsm[k] = W[k];
    __syncthreads();
    if (i >= NN) return;
    const int s = g_offr[i], e = g_offr[i + 1];
    float sum = 0.f;  // lane-parallel over edges
    for (int p = s + lane; p < e; p += 32) sum += g_S[g_adjr[p]];
    float hd = warpsum(sum) * g_cntinv[i];
    float h = g_Bf[i * HID + lane];
    float sc = warpsum(h * w_ws[64 + lane]) + g_T[i] + hd;
    sc = 1.0f / (1.0f + expf(-sc));
    float hnew = (1.0f - sc) * h + sc * g_x0[i * HID + lane];
    // fused next-layer GEMM: G = (hnew @ W) * dinv
    float g = 0.f;
    #pragma unroll
    for (int t = 0; t < HID; t++)
        g = fmaf(__shfl_sync(0xffffffffu, hnew, t), Wsm[t * HID + lane], g);
    g_G[i * HID + lane] = g * g_dinv[i];
}

// ---------------- last block: same but writes A (fp32) for the classifier ----------------
__global__ void k4_score_last(const float* __restrict__ w_ws) {
    const int lane = threadIdx.x & 31;
    const int i = (blockIdx.x * blockDim.x + threadIdx.x) >> 5;
    if (i >= NN) return;
    const int s = g_offr[i], e = g_offr[i + 1];
    float sum = 0.f;
    for (int p = s + lane; p < e; p += 32) sum += g_S[g_adjr[p]];
    float hd = warpsum(sum) * g_cntinv[i];
    float h = g_Bf[i * HID + lane];
    float sc = warpsum(h * w_ws[64 + lane]) + g_T[i] + hd;
    sc = 1.0f / (1.0f + expf(-sc));
    g_A[i * HID + lane] = (1.0f - sc) * h + sc * g_x0[i * HID + lane];
}

// ---------------- final classifier GEMM: A@Wl*dinv -> G40 ----------------
__global__ void k1_final(const float* __restrict__ Wl) {
    __shared__ float Wsm[HID * NCLS];
    const int tid = threadIdx.x;
    const int lane = tid & 31;
    const int i = (blockIdx.x * blockDim.x + tid) >> 5;
    for (int k = tid; k < HID * NCLS; k += blockDim.x) Wsm[k] = Wl[k];
    __syncthreads();
    float hv = g_A[i * HID + lane];
    float acc0 = 0.f, acc1 = 0.f;
    #pragma unroll
    for (int t = 0; t < HID; t++) {
        float xv = __shfl_sync(0xffffffffu, hv, t);
        acc0 = fmaf(xv, Wsm[t * NCLS + lane], acc0);
        if (lane < 8) acc1 = fmaf(xv, Wsm[t * NCLS + 32 + lane], acc1);
    }
    float dv = g_dinv[i];
    g_G40[i * NCLS + lane] = acc0 * dv;
    if (lane < 8) g_G40[i * NCLS + 32 + lane] = acc1 * dv;
}

// ---------------- final GCN aggregate -> out ----------------
__global__ void k2_final(const float* __restrict__ bl, float* __restrict__ out) {
    const int lane = threadIdx.x & 31;
    const int i = (blockIdx.x * blockDim.x + threadIdx.x) >> 5;
    if (i >= NN) return;
    float acc0 = g_G40[i * NCLS + lane];
    float acc1 = (lane < 8) ? g_G40[i * NCLS + 32 + lane] : 0.f;
    const int s = g_offc[i], e = g_offc[i + 1];
    for (int p = s; p < e; p++) {
        int idx = g_adjc[p];
        acc0 += g_G40[idx * NCLS + lane];
        if (lane < 8) acc1 += g_G40[idx * NCLS + 32 + lane];
    }
    float dv = g_dinv[i];
    out[i * NCLS + lane] = dv * acc0 + bl[lane];
    if (lane < 8) out[i * NCLS + 32 + lane] = dv * acc1 + bl[32 + lane];
}

// ---------------- host ----------------
extern "C" void kernel_launch(void* const* d_in, const int* in_sizes, int n_in,
                              void* d_out, int out_size) {
    const float* x    = (const float*)d_in[0];
    const int*   ei   = (const int*)d_in[1];
    const float* W0   = (const float*)d_in[2];
    const float* b0   = (const float*)d_in[3];
    const float* Whh  = (const float*)d_in[4];
    const float* bhh  = (const float*)d_in[5];
    const float* Wl   = (const float*)d_in[6];
    const float* bl   = (const float*)d_in[7];
    const float* lng0 = (const float*)d_in[8];
    const float* lnb0 = (const float*)d_in[9];
    const float* lngm = (const float*)d_in[10];
    const float* lnbm = (const float*)d_in[11];
    const float* w_ws = (const float*)d_in[12];
    const float* Wres = (const float*)d_in[13];
    const float* rg   = (const float*)d_in[14];
    const float* rb   = (const float*)d_in[15];
    float* out = (float*)d_out;

    const int nodeBlocks = (NN + 255) / 256;
    const int warpBlocks = (NN * 32 + 255) / 256;  // warp-per-node, 8 nodes/block

    // CSR build
    zero_deg<<<nodeBlocks, 256>>>();
    hist_edges<<<2048, 256>>>(ei);
    scan_two<<<1, 1024>>>();
    node_init<<<nodeBlocks, 256>>>();
    scatter_edges<<<2048, 256>>>(ei);

    // first layer
    kfirst<<<warpBlocks, 256>>>(x, W0, Wres, rg, rb);

    for (int l = 0; l <= NMID; l++) {  // blocks 0..30
        const float* b   = (l == 0) ? b0   : bhh  + (l - 1) * HID;
        const float* gam = (l == 0) ? lng0 : lngm + (l - 1) * HID;
        const float* bet = (l == 0) ? lnb0 : lnbm + (l - 1) * HID;
        k2_gcn_ln<<<warpBlocks, 256>>>(b, gam, bet);
        k3_mean<<<warpBlocks, 256>>>(w_ws);
        if (l < NMID) {
            k4_score_gemm<<<warpBlocks, 256>>>(w_ws, Whh + l * HID * HID);
        } else {
            k4_score_last<<<warpBlocks, 256>>>(w_ws);
        }
    }
    k1_final<<<warpBlocks, 256>>>(Wl);
    k2_final<<<warpBlocks, 256>>>(bl, out);
}

// round 6
// speedup vs baseline: 1.2396x; 1.0474x over previous
#include <cuda_runtime.h>
#include <cuda_fp16.h>
#include <math.h>

#define NN 50000
#define IN_DIM 256
#define HID 32
#define NCLS 40
#define NEDGE 1600000
#define NMID 30
#define ADJCAP (NEDGE + 8 * NN)   // rows padded to multiples of 8

// ---------------- device scratch (no allocations allowed) ----------------
__device__ int    g_degc[NN], g_degr[NN];
__device__ int    g_offc[NN + 1], g_offr[NN + 1];   // 8-aligned row starts
__device__ int    g_curc[NN], g_curr[NN];
__device__ __align__(16) int g_adjc[ADJCAP];
__device__ __align__(16) int g_adjr[ADJCAP];
__device__ float  g_dinv[NN], g_cntinv[NN];
__device__ float  g_x0[NN * HID];
__device__ float  g_A [NN * HID];    // final-layer input (written once)
__device__ __align__(16) float  g_G [NN * HID];   // (h @ W) * dinv — gathered fp32
__device__ __align__(16) float  g_Bf[NN * HID];   // LN(relu(gcn)) — node-local fp32
__device__ __align__(16) __half g_Bh[NN * HID];   // fp16 gather copy (score path)
__device__ float  g_S[NN];           // s[j]=Σ|B-hm|·w2  — scalar gathered fp32
__device__ float  g_T[NN];           // t[i]=Σ hm·h·w0   — node-local scalar
__device__ float  g_G40[NN * NCLS];  // final (h @ Wl) * dinv

__device__ __forceinline__ float warpsum(float v) {
    #pragma unroll
    for (int o = 16; o > 0; o >>= 1) v += __shfl_xor_sync(0xffffffffu, v, o);
    return v;
}

// ---------------- setup: degrees, scans, CSR ----------------
__global__ void zero_deg() {
    for (int i = blockIdx.x * blockDim.x + threadIdx.x; i < NN;
         i += gridDim.x * blockDim.x) {
        g_degc[i] = 0;
        g_degr[i] = 0;
    }
}

__global__ void hist_edges(const int* __restrict__ ei) {
    for (int e = blockIdx.x * blockDim.x + threadIdx.x; e < NEDGE;
         e += gridDim.x * blockDim.x) {
        atomicAdd(&g_degr[ei[e]], 1);          // row
        atomicAdd(&g_degc[ei[NEDGE + e]], 1);  // col
    }
}

// one block, 1024 threads: exclusive scan of (deg rounded up to 8)
__global__ void scan_two() {
    __shared__ int wsum[33];
    const int tid = threadIdx.x, lane = tid & 31, wid = tid >> 5;
    for (int arr = 0; arr < 2; arr++) {
        const int* src = arr ? g_degr : g_degc;
        int*       dst = arr ? g_offr : g_offc;
        int run = 0;
        for (int base = 0; base < NN; base += 1024) {
            int i = base + tid;
            int v = (i < NN) ? ((src[i] + 7) & ~7) : 0;  // pad rows to 8
            int inc = v;
            #pragma unroll
            for (int o = 1; o < 32; o <<= 1) {
                int t = __shfl_up_sync(0xffffffffu, inc, o);
                if (lane >= o) inc += t;
            }
            if (lane == 31) wsum[wid] = inc;
            __syncthreads();
            if (wid == 0) {
                int s = wsum[lane];
                int si = s;
                #pragma unroll
                for (int o = 1; o < 32; o <<= 1) {
                    int t = __shfl_up_sync(0xffffffffu, si, o);
                    if (lane >= o) si += t;
                }
                wsum[lane] = si - s;            // exclusive warp prefix
                if (lane == 31) wsum[32] = si;  // chunk total
            }
            __syncthreads();
            if (i < NN) dst[i] = run + wsum[wid] + inc - v;
            run += wsum[32];
            __syncthreads();
        }
        if (tid == 0) dst[NN] = run;
        __syncthreads();
    }
}

__global__ void node_init() {
    for (int i = blockIdx.x * blockDim.x + threadIdx.x; i < NN;
         i += gridDim.x * blockDim.x) {
        g_curc[i] = g_offc[i];
        g_curr[i] = g_offr[i];
        g_dinv[i] = rsqrtf((float)(g_degc[i] + 1));  // +1 self loop
        g_cntinv[i] = 1.0f / fmaxf((float)g_degr[i], 1.0f);
    }
}

__global__ void scatter_edges(const int* __restrict__ ei) {
    for (int e = blockIdx.x * blockDim.x + threadIdx.x; e < NEDGE;
         e += gridDim.x * blockDim.x) {
        int r = ei[e];
        int c = ei[NEDGE + e];
        int p = atomicAdd(&g_curc[c], 1);
        g_adjc[p] = r;  // CSR by col (gcn target), stores source row
        int q = atomicAdd(&g_curr[r], 1);
        g_adjr[q] = c;  // CSR by row (mean_agg target), stores source col
    }
}

// ---------------- first layer: x@W0*dinv -> G ; LN(relu(x@W_res)) -> x0 ----------------
__global__ void kfirst(const float* __restrict__ x, const float* __restrict__ W0,
                       const float* __restrict__ Wres, const float* __restrict__ rg,
                       const float* __restrict__ rb) {
    __shared__ float Wsm[IN_DIM * HID];  // 32 KB
    const int tid = threadIdx.x;
    const int lane = tid & 31;
    const int i = (blockIdx.x * blockDim.x + tid) >> 5;  // node (grid exact)

    for (int k = tid; k < IN_DIM * HID; k += blockDim.x) Wsm[k] = W0[k];

    float xr[8];
    #pragma unroll
    for (int j = 0; j < 8; j++) xr[j] = x[i * IN_DIM + j * 32 + lane];
    __syncthreads();

    float acc0 = 0.f;
    #pragma unroll
    for (int j = 0; j < 8; j++) {
        #pragma unroll
        for (int t = 0; t < 32; t++) {
            float xv = __shfl_sync(0xffffffffu, xr[j], t);
            acc0 = fmaf(xv, Wsm[(j * 32 + t) * HID + lane], acc0);
        }
    }
    __syncthreads();
    for (int k = tid; k < IN_DIM * HID; k += blockDim.x) Wsm[k] = Wres[k];
    __syncthreads();

    float acc1 = 0.f;
    #pragma unroll
    for (int j = 0; j < 8; j++) {
        #pragma unroll
        for (int t = 0; t < 32; t++) {
            float xv = __shfl_sync(0xffffffffu, xr[j], t);
            acc1 = fmaf(xv, Wsm[(j * 32 + t) * HID + lane], acc1);
        }
    }

    g_G[i * HID + lane] = acc0 * g_dinv[i];

    float r = fmaxf(acc1, 0.f);
    float m = warpsum(r) * (1.f / HID);
    float d = r - m;
    float var = warpsum(d * d) * (1.f / HID);
    g_x0[i * HID + lane] = d * rsqrtf(var + 1e-5f) * rg[lane] + rb[lane];
}

// ---------------- GCN aggregate + bias + relu + LN -> Bf/Bh (dual-edge) ----------------
__global__ void k2_gcn_ln(const float* __restrict__ b, const float* __restrict__ gam,
                          const float* __restrict__ bet) {
    const int lane = threadIdx.x & 31;
    const int sub = lane & 15;     // feature-pair index
    const int half = lane >> 4;    // which edge of the pair
    const int i = (blockIdx.x * blockDim.x + threadIdx.x) >> 5;
    if (i >= NN) return;
    const float2* G2 = (const float2*)g_G;
    const int s = g_offc[i];
    const int e = s + g_degc[i];
    int p = s;
    float2 a0 = {0.f, 0.f}, a1 = {0.f, 0.f}, a2 = {0.f, 0.f}, a3 = {0.f, 0.f};
    for (; p + 8 <= e; p += 8) {
        int4 ia = *(const int4*)&g_adjc[p];
        int4 ib = *(const int4*)&g_adjc[p + 4];
        int j0 = half ? ia.y : ia.x;
        int j1 = half ? ia.w : ia.z;
        int j2 = half ? ib.y : ib.x;
        int j3 = half ? ib.w : ib.z;
        float2 v0 = G2[j0 * 16 + sub];
        float2 v1 = G2[j1 * 16 + sub];
        float2 v2 = G2[j2 * 16 + sub];
        float2 v3 = G2[j3 * 16 + sub];
        a0.x += v0.x; a0.y += v0.y;
        a1.x += v1.x; a1.y += v1.y;
        a2.x += v2.x; a2.y += v2.y;
        a3.x += v3.x; a3.y += v3.y;
    }
    for (; p < e; p += 2) {
        if (p + half < e) {
            int j = g_adjc[p + half];
            float2 v = G2[j * 16 + sub];
            a0.x += v.x; a0.y += v.y;
        }
    }
    float sx = (a0.x + a1.x) + (a2.x + a3.x);
    float sy = (a0.y + a1.y) + (a2.y + a3.y);
    sx += __shfl_xor_sync(0xffffffffu, sx, 16);   // combine halves
    sy += __shfl_xor_sync(0xffffffffu, sy, 16);
    float2 self = G2[i * 16 + sub];               // self loop
    sx += self.x;
    sy += self.y;
    const float dv = g_dinv[i];
    float2 bb = ((const float2*)b)[sub];
    float v0 = fmaxf(fmaf(dv, sx, bb.x), 0.f);
    float v1 = fmaxf(fmaf(dv, sy, bb.y), 0.f);
    // LN over 32 features; lanes duplicate features across halves -> x0.5
    float m = warpsum(v0 + v1) * (0.5f / HID);
    float d0 = v0 - m, d1 = v1 - m;
    float var = warpsum(d0 * d0 + d1 * d1) * (0.5f / HID);
    float rs = rsqrtf(var + 1e-5f);
    float2 gg = ((const float2*)gam)[sub];
    float2 be = ((const float2*)bet)[sub];
    float o0 = d0 * rs * gg.x + be.x;
    float o1 = d1 * rs * gg.y + be.y;
    if (half == 0) {
        ((float2*)g_Bf)[i * 16 + sub] = make_float2(o0, o1);
        ((__half2*)g_Bh)[i * 16 + sub] = __floats2half2_rn(o0, o1);
    }
}

// ---------------- mean_agg(B)->hm ; scalars s=Σ|B-hm|·w2, t=Σ hm·h·w0 (dual-edge) ----------------
__global__ void k3_mean(const float* __restrict__ w_ws) {
    const int lane = threadIdx.x & 31;
    const int sub = lane & 15;
    const int half = lane >> 4;
    const int i = (blockIdx.x * blockDim.x + threadIdx.x) >> 5;
    if (i >= NN) return;
    const __half2* B2 = (const __half2*)g_Bh;
    const int s = g_offr[i];
    const int e = s + g_degr[i];
    int p = s;
    float2 a0 = {0.f, 0.f}, a1 = {0.f, 0.f}, a2 = {0.f, 0.f}, a3 = {0.f, 0.f};
    for (; p + 8 <= e; p += 8) {
        int4 ia = *(const int4*)&g_adjr[p];
        int4 ib = *(const int4*)&g_adjr[p + 4];
        int j0 = half ? ia.y : ia.x;
        int j1 = half ? ia.w : ia.z;
        int j2 = half ? ib.y : ib.x;
        int j3 = half ? ib.w : ib.z;
        float2 v0 = __half22float2(B2[j0 * 16 + sub]);
        float2 v1 = __half22float2(B2[j1 * 16 + sub]);
        float2 v2 = __half22float2(B2[j2 * 16 + sub]);
        float2 v3 = __half22float2(B2[j3 * 16 + sub]);
        a0.x += v0.x; a0.y += v0.y;
        a1.x += v1.x; a1.y += v1.y;
        a2.x += v2.x; a2.y += v2.y;
        a3.x += v3.x; a3.y += v3.y;
    }
    for (; p < e; p += 2) {
        if (p + half < e) {
            float2 v = __half22float2(B2[g_adjr[p + half] * 16 + sub]);
            a0.x += v.x; a0.y += v.y;
        }
    }
    float sx = (a0.x + a1.x) + (a2.x + a3.x);
    float sy = (a0.y + a1.y) + (a2.y + a3.y);
    sx += __shfl_xor_sync(0xffffffffu, sx, 16);
    sy += __shfl_xor_sync(0xffffffffu, sy, 16);
    const float ci = g_cntinv[i];
    float hm0 = sx * ci, hm1 = sy * ci;
    float2 h = ((const float2*)g_Bf)[i * 16 + sub];
    float2 w0 = ((const float2*)w_ws)[sub];
    float2 w2 = ((const float2*)(w_ws + HID))[sub];
    float svp = fabsf(h.x - hm0) * w2.x + fabsf(h.y - hm1) * w2.y;
    float tvp = hm0 * h.x * w0.x + hm1 * h.y * w0.y;
    float sv = warpsum(svp) * 0.5f;   // halves duplicate
    float tv = warpsum(tvp) * 0.5f;
    if (lane == 0) {
        g_S[i] = sv;
        g_T[i] = tv;
    }
}

// ---------------- scalar gather s -> hd ; score ; gate ; fused GEMM -> G ----------------
__global__ void k4_score_gemm(const float* __restrict__ w_ws, const float* __restrict__ W) {
    __shared__ float Wsm[HID * HID];
    const int tid = threadIdx.x;
    const int lane = tid & 31;
    const int i = (blockIdx.x * blockDim.x + tid) >> 5;
    for (int k = tid; k < HID * HID; k += blockDim.x) Wsm[k] = W[k];
    __syncthreads();
    if (i >= NN) return;
    const int s = g_offr[i];
    const int e = s + g_degr[i];
    float sum = 0.f;  // lane-parallel over edges
    for (int p = s + lane; p < e; p += 32) sum += __ldg(&g_S[g_adjr[p]]);
    float hd = warpsum(sum) * g_cntinv[i];
    float h = g_Bf[i * HID + lane];
    float sc = warpsum(h * w_ws[64 + lane]) + g_T[i] + hd;
    sc = 1.0f / (1.0f + expf(-sc));
    float hnew = (1.0f - sc) * h + sc * g_x0[i * HID + lane];
    // fused next-layer GEMM: G = (hnew @ W) * dinv
    float g = 0.f;
    #pragma unroll
    for (int t = 0; t < HID; t++)
        g = fmaf(__shfl_sync(0xffffffffu, hnew, t), Wsm[t * HID + lane], g);
    g_G[i * HID + lane] = g * g_dinv[i];
}

// ---------------- last block: same but writes A (fp32) for the classifier ----------------
__global__ void k4_score_last(const float* __restrict__ w_ws) {
    const int lane = threadIdx.x & 31;
    const int i = (blockIdx.x * blockDim.x + threadIdx.x) >> 5;
    if (i >= NN) return;
    const int s = g_offr[i];
    const int e = s + g_degr[i];
    float sum = 0.f;
    for (int p = s + lane; p < e; p += 32) sum += __ldg(&g_S[g_adjr[p]]);
    float hd = warpsum(sum) * g_cntinv[i];
    float h = g_Bf[i * HID + lane];
    float sc = warpsum(h * w_ws[64 + lane]) + g_T[i] + hd;
    sc = 1.0f / (1.0f + expf(-sc));
    g_A[i * HID + lane] = (1.0f - sc) * h + sc * g_x0[i * HID + lane];
}

// ---------------- final classifier GEMM: A@Wl*dinv -> G40 ----------------
__global__ void k1_final(const float* __restrict__ Wl) {
    __shared__ float Wsm[HID * NCLS];
    const int tid = threadIdx.x;
    const int lane = tid & 31;
    const int i = (blockIdx.x * blockDim.x + tid) >> 5;
    for (int k = tid; k < HID * NCLS; k += blockDim.x) Wsm[k] = Wl[k];
    __syncthreads();
    float hv = g_A[i * HID + lane];
    float acc0 = 0.f, acc1 = 0.f;
    #pragma unroll
    for (int t = 0; t < HID; t++) {
        float xv = __shfl_sync(0xffffffffu, hv, t);
        acc0 = fmaf(xv, Wsm[t * NCLS + lane], acc0);
        if (lane < 8) acc1 = fmaf(xv, Wsm[t * NCLS + 32 + lane], acc1);
    }
    float dv = g_dinv[i];
    g_G40[i * NCLS + lane] = acc0 * dv;
    if (lane < 8) g_G40[i * NCLS + 32 + lane] = acc1 * dv;
}

// ---------------- final GCN aggregate -> out ----------------
__global__ void k2_final(const float* __restrict__ bl, float* __restrict__ out) {
    const int lane = threadIdx.x & 31;
    const int i = (blockIdx.x * blockDim.x + threadIdx.x) >> 5;
    if (i >= NN) return;
    float acc0 = g_G40[i * NCLS + lane];
    float acc1 = (lane < 8) ? g_G40[i * NCLS + 32 + lane] : 0.f;
    const int s = g_offc[i];
    const int e = s + g_degc[i];
    for (int p = s; p < e; p++) {
        int idx = g_adjc[p];
        acc0 += g_G40[idx * NCLS + lane];
        if (lane < 8) acc1 += g_G40[idx * NCLS + 32 + lane];
    }
    float dv = g_dinv[i];
    out[i * NCLS + lane] = dv * acc0 + bl[lane];
    if (lane < 8) out[i * NCLS + 32 + lane] = dv * acc1 + bl[32 + lane];
}

// ---------------- host ----------------
extern "C" void kernel_launch(void* const* d_in, const int* in_sizes, int n_in,
                              void* d_out, int out_size) {
    const float* x    = (const float*)d_in[0];
    const int*   ei   = (const int*)d_in[1];
    const float* W0   = (const float*)d_in[2];
    const float* b0   = (const float*)d_in[3];
    const float* Whh  = (const float*)d_in[4];
    const float* bhh  = (const float*)d_in[5];
    const float* Wl   = (const float*)d_in[6];
    const float* bl   = (const float*)d_in[7];
    const float* lng0 = (const float*)d_in[8];
    const float* lnb0 = (const float*)d_in[9];
    const float* lngm = (const float*)d_in[10];
    const float* lnbm = (const float*)d_in[11];
    const float* w_ws = (const float*)d_in[12];
    const float* Wres = (const float*)d_in[13];
    const float* rg   = (const float*)d_in[14];
    const float* rb   = (const float*)d_in[15];
    float* out = (float*)d_out;

    const int nodeBlocks = (NN + 255) / 256;
    const int warpBlocks = (NN * 32 + 255) / 256;  // warp-per-node, 8 nodes/block

    // CSR build
    zero_deg<<<nodeBlocks, 256>>>();
    hist_edges<<<2048, 256>>>(ei);
    scan_two<<<1, 1024>>>();
    node_init<<<nodeBlocks, 256>>>();
    scatter_edges<<<2048, 256>>>(ei);

    // first layer
    kfirst<<<warpBlocks, 256>>>(x, W0, Wres, rg, rb);

    for (int l = 0; l <= NMID; l++) {  // blocks 0..30
        const float* b   = (l == 0) ? b0   : bhh  + (l - 1) * HID;
        const float* gam = (l == 0) ? lng0 : lngm + (l - 1) * HID;
        const float* bet = (l == 0) ? lnb0 : lnbm + (l - 1) * HID;
        k2_gcn_ln<<<warpBlocks, 256>>>(b, gam, bet);
        k3_mean<<<warpBlocks, 256>>>(w_ws);
        if (l < NMID) {
            k4_score_gemm<<<warpBlocks, 256>>>(w_ws, Whh + l * HID * HID);
        } else {
            k4_score_last<<<warpBlocks, 256>>>(w_ws);
        }
    }
    k1_final<<<warpBlocks, 256>>>(Wl);
    k2_final<<<warpBlocks, 256>>>(bl, out);
}